// round 11
// baseline (speedup 1.0000x reference)
#include <cuda_runtime.h>
#include <cstdint>

#define NB    64
#define NC    256
#define NP    4096        // H*W
#define NE    4
#define NO    65          // OUT = CELL*CELL+1
#define NOP   72          // padded OUT
#define NTILE 16          // 256-pixel tiles per batch

// k3 dynamic smem layout (bytes): 4-deep ring of 16-channel chunks
#define XS_STR   264                          // floats per x row (bank spread 8j+q)
#define WS_STR   76                           // uint2 per w row
#define XBUF     (16 * XS_STR * 4)            // 16896
#define WBUF     (8 * WS_STR * 8)             // 4864
#define OFF_X    0
#define OFF_W    (4 * XBUF)                   // 67584
#define OFF_BIAS (OFF_W + 4 * WBUF)           // 87040
#define OFF_SRED (OFF_BIAS + 512)             // 87552
#define SMEM_K3  (OFF_SRED + 8 * 72 * 8)      // 92160

// ---------------- device scratch ----------------
__device__ float  g_pooled[NB * NC];
__device__ int    g_idx[NB];
__device__ float2 g_part2[NO * NB * NTILE];
__device__ float  g_scale[NO];
__device__ float  g_shift[NO];
__device__ __align__(16) uint2 g_Wp[NE * 128 * NOP];   // [e][pair-row][n]

// ---------------- helpers ----------------
__device__ __forceinline__ uint32_t f2tf32(float f) {
    uint32_t r;
    asm("cvt.rna.tf32.f32 %0, %1;" : "=r"(r) : "f"(f));
    return r;
}
__device__ __forceinline__ uint32_t smem_u32(const void* p) {
    uint32_t a;
    asm("{ .reg .u64 t; cvta.to.shared.u64 t, %1; cvt.u32.u64 %0, t; }" : "=r"(a) : "l"(p));
    return a;
}
// D(16x8) += A(16x8,row) * B(8x8,col), tf32 inputs, f32 accum
__device__ __forceinline__ void mma8(float* d, uint2 a02, uint2 a13, uint2 b) {
    asm("mma.sync.aligned.m16n8k8.row.col.f32.tf32.tf32.f32 "
        "{%0,%1,%2,%3}, {%4,%5,%6,%7}, {%8,%9}, {%0,%1,%2,%3};"
        : "+f"(d[0]), "+f"(d[1]), "+f"(d[2]), "+f"(d[3])
        : "r"(a02.x), "r"(a13.x), "r"(a02.y), "r"(a13.y), "r"(b.x), "r"(b.y));
}
#define CP16(dst_u32, src_ptr) \
    asm volatile("cp.async.cg.shared.global [%0], [%1], 16;" :: "r"(dst_u32), "l"(src_ptr) : "memory")
#define CP_COMMIT() asm volatile("cp.async.commit_group;" ::: "memory")
#define CP_WAIT(N)  asm volatile("cp.async.wait_group %0;" :: "n"(N) : "memory")

// ---------------- K0: pack W[e] into tf32 (k,k+4)-pair rows ----------------
// pair-row r (0..127): c=r>>4, rr=r&15 -> channels (c*32 + (rr>>2)*8 + (rr&3), +4)
__global__ void k0_wprep(const float* __restrict__ w) {
    int idx = blockIdx.x * 256 + threadIdx.x;       // NE*128*72 = 36864
    int e = idx / (128 * NOP);
    int rem = idx - e * (128 * NOP);
    int r = rem / NOP;
    int n = rem - r * NOP;
    int c = r >> 4, rr = r & 15;
    int k = c * 32 + (rr >> 2) * 8 + (rr & 3);
    float lo = (n < NO) ? w[(e * NC + k) * NO + n] : 0.f;
    float hi = (n < NO) ? w[(e * NC + k + 4) * NO + n] : 0.f;
    g_Wp[idx] = make_uint2(f2tf32(lo), f2tf32(hi));
}

// ---------------- K1: pooled[b][c] = mean over pixels of relu(x) ----------------
__global__ void k1_pool(const float* __restrict__ x) {
    int plane = blockIdx.x;
    const float4* base = (const float4*)(x + (long)plane * NP);
    float s = 0.f;
    #pragma unroll
    for (int i = 0; i < 8; i++) {
        float4 v = base[threadIdx.x + 128 * i];
        s += fmaxf(v.x, 0.f) + fmaxf(v.y, 0.f) + fmaxf(v.z, 0.f) + fmaxf(v.w, 0.f);
    }
    #pragma unroll
    for (int o = 16; o; o >>= 1) s += __shfl_xor_sync(0xffffffffu, s, o);
    __shared__ float red[4];
    if ((threadIdx.x & 31) == 0) red[threadIdx.x >> 5] = s;
    __syncthreads();
    if (threadIdx.x == 0)
        g_pooled[plane] = (red[0] + red[1] + red[2] + red[3]) * (1.f / NP);
}

// ---------------- K2: gate -> argmax expert, lb_loss ----------------
__global__ void k2_gate(const float* __restrict__ w_gate,
                        const float* __restrict__ b_gate,
                        float* __restrict__ loss_out) {
    int b = threadIdx.x;                          // 64 threads
    float lg[NE];
    #pragma unroll
    for (int e = 0; e < NE; e++) lg[e] = b_gate[e];
    const float* pr = g_pooled + b * NC;
    for (int c = 0; c < NC; c++) {
        float pv = pr[c];
        #pragma unroll
        for (int e = 0; e < NE; e++) lg[e] += pv * w_gate[c * NE + e];
    }
    int best = 0; float bv = lg[0];
    #pragma unroll
    for (int e = 1; e < NE; e++)
        if (lg[e] > bv) { bv = lg[e]; best = e; }
    g_idx[b] = best;

    __shared__ int sidx[NB];
    sidx[b] = best;
    __syncthreads();
    if (b == 0) {
        int cnt[NE] = {0, 0, 0, 0};
        for (int i = 0; i < NB; i++) cnt[sidx[i]]++;
        float u[NE]; float s = 0.f;
        #pragma unroll
        for (int e = 0; e < NE; e++) { u[e] = (float)cnt[e] / (float)NB + 1e-6f; s += u[e]; }
        float lb = 0.f;
        #pragma unroll
        for (int e = 0; e < NE; e++) {
            float uu = u[e] / s;
            lb += uu * (logf(uu) - logf(0.25f));
        }
        loss_out[0] = lb;
    }
}

// ---------------- K3: 4-deep cp.async ring, tf32 GEMM + fused BN partials ----------------
// chunk = 16 channels; 16 chunks; ring buffer 4; wait_group 2 -> 3 chunks in flight
#define ISSUE(c, buf) do { \
    const float* _xsrc = xb + ((size_t)(c) * 16 + xrow) * NP + xcol * 4; \
    uint32_t _xdst = sbase + OFF_X + (buf) * XBUF + xrow * (XS_STR * 4) + xcol * 16; \
    _Pragma("unroll") \
    for (int _i = 0; _i < 4; _i++) \
        CP16(_xdst + _i * 256, _xsrc + _i * 64); \
    _Pragma("unroll") \
    for (int _it = 0; _it < 2; _it++) { \
        int _ii = tid + _it * 256; \
        if (_ii < 288) { \
            int _r = _ii / 36, _cc = _ii - _r * 36; \
            CP16(sbase + OFF_W + (buf) * WBUF + _r * (WS_STR * 8) + _cc * 16, \
                 (const char*)(wp + ((c) * 8 + _r) * NOP + _cc * 2)); \
        } \
    } \
    CP_COMMIT(); \
} while (0)

#define MMACHUNK(buf) do { \
    const float* _xsr = (const float*)(sm + OFF_X + (buf) * XBUF); \
    const uint2* _wsp = (const uint2*)(sm + OFF_W + (buf) * WBUF); \
    _Pragma("unroll") \
    for (int _g = 0; _g < 2; _g++) { \
        const float* _xj = _xsr + (_g * 8 + j) * XS_STR + warp_m; \
        uint2 a00, a01, a10, a11; \
        a00.x = f2tf32(fmaxf(_xj[q],      0.f)); a00.y = f2tf32(fmaxf(_xj[4 * XS_STR + q],      0.f)); \
        a01.x = f2tf32(fmaxf(_xj[q + 8],  0.f)); a01.y = f2tf32(fmaxf(_xj[4 * XS_STR + q + 8],  0.f)); \
        a10.x = f2tf32(fmaxf(_xj[q + 16], 0.f)); a10.y = f2tf32(fmaxf(_xj[4 * XS_STR + q + 16], 0.f)); \
        a11.x = f2tf32(fmaxf(_xj[q + 24], 0.f)); a11.y = f2tf32(fmaxf(_xj[4 * XS_STR + q + 24], 0.f)); \
        const uint2* _wrow = _wsp + (_g * 4 + j) * WS_STR + q; \
        _Pragma("unroll") \
        for (int _nt = 0; _nt < 9; _nt++) { \
            uint2 _bb = _wrow[_nt * 8]; \
            mma8(acc[0][_nt], a00, a01, _bb); \
            mma8(acc[1][_nt], a10, a11, _bb); \
        } \
    } \
} while (0)

__global__ __launch_bounds__(256, 2) void k3_mma(const float* __restrict__ x,
                                                 const float* __restrict__ b_experts,
                                                 float* __restrict__ ylog) {
    extern __shared__ __align__(16) char sm[];
    float*  bias_s = (float*)(sm + OFF_BIAS);
    float2* sred   = (float2*)(sm + OFF_SRED);
    uint32_t sbase = smem_u32(sm);

    int tid = threadIdx.x, lane = tid & 31, wid = tid >> 5;
    int j = lane & 3, q = lane >> 2;
    int b = blockIdx.y, tile = blockIdx.x;
    int p0 = tile * 256;
    int e = g_idx[b];
    int warp_m = wid * 32;

    const float* xb = x + (size_t)b * NC * NP + p0;
    const uint2* wp = g_Wp + e * (128 * NOP);

    if (tid < NOP) bias_s[tid] = (tid < NO) ? b_experts[e * NO + tid] : 0.f;

    // cp.async x mapping: 16 rows x 64 float4; 16 threads/row, 4 iters
    int xrow = tid >> 4;
    int xcol = tid & 15;

    float acc[2][9][4];
    #pragma unroll
    for (int mt = 0; mt < 2; mt++)
        #pragma unroll
        for (int nt = 0; nt < 9; nt++)
            #pragma unroll
            for (int r = 0; r < 4; r++) acc[mt][nt][r] = 0.f;

    ISSUE(0, 0);
    ISSUE(1, 1);
    ISSUE(2, 2);

    #pragma unroll 4
    for (int c = 0; c < 16; c++) {
        CP_WAIT(2);
        __syncthreads();
        MMACHUNK(c & 3);
        __syncthreads();
        if (c + 3 < 16) {
            ISSUE(c + 3, (c + 3) & 3);
        } else {
            CP_COMMIT();          // empty group keeps wait_group accounting uniform
        }
    }

    // ---- epilogue: bias, store y, fused per-channel sum/sumsq partials ----
    float sE[9], qE[9], sO[9], qO[9];
    int prow = p0 + warp_m + q;
    #pragma unroll
    for (int nt = 0; nt < 9; nt++) {
        int o0 = nt * 8 + 2 * j;
        float b0 = bias_s[o0], b1 = bias_s[o0 + 1];
        float v00 = acc[0][nt][0] + b0, v02 = acc[0][nt][2] + b0;
        float v10 = acc[1][nt][0] + b0, v12 = acc[1][nt][2] + b0;
        float v01 = acc[0][nt][1] + b1, v03 = acc[0][nt][3] + b1;
        float v11 = acc[1][nt][1] + b1, v13 = acc[1][nt][3] + b1;
        if (o0 < NO) {
            float* d = ylog + ((size_t)b * NO + o0) * NP + prow;
            d[0] = v00; d[8] = v02; d[16] = v10; d[24] = v12;
        }
        if (o0 + 1 < NO) {
            float* d = ylog + ((size_t)b * NO + o0 + 1) * NP + prow;
            d[0] = v01; d[8] = v03; d[16] = v11; d[24] = v13;
        }
        sE[nt] = v00 + v02 + v10 + v12;
        qE[nt] = v00 * v00 + v02 * v02 + v10 * v10 + v12 * v12;
        sO[nt] = v01 + v03 + v11 + v13;
        qO[nt] = v01 * v01 + v03 * v03 + v11 * v11 + v13 * v13;
    }
    #pragma unroll
    for (int nt = 0; nt < 9; nt++) {
        #pragma unroll
        for (int off = 4; off < 32; off <<= 1) {
            sE[nt] += __shfl_xor_sync(0xffffffffu, sE[nt], off);
            qE[nt] += __shfl_xor_sync(0xffffffffu, qE[nt], off);
            sO[nt] += __shfl_xor_sync(0xffffffffu, sO[nt], off);
            qO[nt] += __shfl_xor_sync(0xffffffffu, qO[nt], off);
        }
    }
    if (q == 0) {        // lanes 0..3 hold warp totals for cols 2j / 2j+1 of each nt
        #pragma unroll
        for (int nt = 0; nt < 9; nt++) {
            sred[wid * NOP + nt * 8 + 2 * j]     = make_float2(sE[nt], qE[nt]);
            sred[wid * NOP + nt * 8 + 2 * j + 1] = make_float2(sO[nt], qO[nt]);
        }
    }
    __syncthreads();
    if (tid < NO) {
        float ts = 0.f, tq = 0.f;
        #pragma unroll
        for (int w = 0; w < 8; w++) {
            float2 v = sred[w * NOP + tid];
            ts += v.x; tq += v.y;
        }
        g_part2[tid * (NB * NTILE) + b * NTILE + tile] = make_float2(ts, tq);
    }
}

// ---------------- K4b: reduce partials, finalize BN scale/shift ----------------
__global__ void k4b_finalize(const float* __restrict__ gamma,
                             const float* __restrict__ beta) {
    int o = blockIdx.x;
    int t = threadIdx.x;                 // 256
    const float2* p = g_part2 + o * (NB * NTILE);
    float s = 0.f, qq = 0.f;
    #pragma unroll
    for (int i = 0; i < 4; i++) {
        float2 v = p[t + 256 * i];
        s += v.x; qq += v.y;
    }
    #pragma unroll
    for (int off = 16; off; off >>= 1) {
        s  += __shfl_xor_sync(0xffffffffu, s, off);
        qq += __shfl_xor_sync(0xffffffffu, qq, off);
    }
    __shared__ float2 red[8];
    if ((t & 31) == 0) red[t >> 5] = make_float2(s, qq);
    __syncthreads();
    if (t == 0) {
        float ts = 0.f, tq = 0.f;
        #pragma unroll
        for (int i = 0; i < 8; i++) { ts += red[i].x; tq += red[i].y; }
        const float inv = 1.f / ((float)NB * (float)NP);
        float mean = ts * inv;
        float var = tq * inv - mean * mean;
        float sc = gamma[o] * rsqrtf(var + 1e-5f);
        g_scale[o] = sc;
        g_shift[o] = beta[o] - mean * sc;
    }
}

// ---------------- K5: normalize logits, softmax, pixel-shuffle prob ----------------
__global__ __launch_bounds__(256) void k5_final(float* __restrict__ ylog,
                                                float* __restrict__ prob) {
    int b = blockIdx.y;
    int h = blockIdx.x * 4 + (threadIdx.x >> 6);
    int w = threadIdx.x & 63;
    long base = ((long)b * NO) * NP + h * 64 + w;

    float v[NO];
    float mx = -1e30f;
    #pragma unroll
    for (int o = 0; o < NO; o++) {
        float y = ylog[base + (long)o * NP];
        y = y * g_scale[o] + g_shift[o];
        ylog[base + (long)o * NP] = y;
        v[o] = y;
        mx = fmaxf(mx, y);
    }
    float sum = 0.f;
    #pragma unroll
    for (int o = 0; o < NO; o++) {
        float ev = __expf(v[o] - mx);
        v[o] = ev;
        sum += ev;
    }
    float inv = 1.f / sum;

    float* pb = prob + (long)b * (512 * 512) + (long)(h * 8) * 512 + w * 8;
    #pragma unroll
    for (int r1 = 0; r1 < 8; r1++) {
        float4 a, c;
        a.x = v[r1 * 8 + 0] * inv; a.y = v[r1 * 8 + 1] * inv;
        a.z = v[r1 * 8 + 2] * inv; a.w = v[r1 * 8 + 3] * inv;
        c.x = v[r1 * 8 + 4] * inv; c.y = v[r1 * 8 + 5] * inv;
        c.z = v[r1 * 8 + 6] * inv; c.w = v[r1 * 8 + 7] * inv;
        *(float4*)(pb + (long)r1 * 512)     = a;
        *(float4*)(pb + (long)r1 * 512 + 4) = c;
    }
}

// ---------------- launch ----------------
extern "C" void kernel_launch(void* const* d_in, const int* in_sizes, int n_in,
                              void* d_out, int out_size) {
    const float* x         = (const float*)d_in[0];
    const float* w_experts = (const float*)d_in[1];
    const float* b_experts = (const float*)d_in[2];
    const float* w_gate    = (const float*)d_in[3];
    const float* b_gate    = (const float*)d_in[4];
    const float* gamma     = (const float*)d_in[5];
    const float* beta      = (const float*)d_in[6];

    float* out  = (float*)d_out;
    float* ylog = out;                              // logits: B*NO*NP
    float* prob = out + (long)NB * NO * NP;         // prob:   B*512*512
    float* loss = prob + (long)NB * 512 * 512;      // lb_loss scalar

    cudaFuncSetAttribute(k3_mma, cudaFuncAttributeMaxDynamicSharedMemorySize, SMEM_K3);

    k0_wprep<<<144, 256>>>(w_experts);
    k1_pool<<<NB * NC, 128>>>(x);
    k2_gate<<<1, 64>>>(w_gate, b_gate, loss);
    k3_mma<<<dim3(NTILE, NB), 256, SMEM_K3>>>(x, b_experts, ylog);
    k4b_finalize<<<NO, 256>>>(gamma, beta);
    k5_final<<<dim3(16, NB), 256>>>(ylog, prob);
}